// round 8
// baseline (speedup 1.0000x reference)
#include <cuda_runtime.h>
#include <cuda_bf16.h>
#include <cstdint>
#include <math.h>

#define B_   16
#define S_   2048
#define D_   128
#define H_   4
#define DH_  32
#define FF_  512
#define L_   4
#define OUT_ 30
#define M_   (B_*S_)   // 32768

// log2(e) / sqrt(32): folded into Q so softmax is a bare ex2
#define QSCALE 0.25506626866f

// ======================= low-level helpers =======================
__device__ __forceinline__ void mma16816(float* d, const uint32_t* a, const uint32_t* b) {
    asm volatile("mma.sync.aligned.m16n8k16.row.col.f32.bf16.bf16.f32 "
        "{%0,%1,%2,%3}, {%4,%5,%6,%7}, {%8,%9}, {%0,%1,%2,%3};"
        : "+f"(d[0]), "+f"(d[1]), "+f"(d[2]), "+f"(d[3])
        : "r"(a[0]), "r"(a[1]), "r"(a[2]), "r"(a[3]), "r"(b[0]), "r"(b[1]));
}
__device__ __forceinline__ uint32_t packbf2(float x, float y) {
    __nv_bfloat162 p = __floats2bfloat162_rn(x, y);
    return *(uint32_t*)&p;
}
__device__ __forceinline__ float ex2f(float x) {
    float y; asm("ex2.approx.f32 %0, %1;" : "=f"(y) : "f"(x)); return y;
}
__device__ __forceinline__ uint32_t cvta_s(const void* p) {
    return (uint32_t)__cvta_generic_to_shared(p);
}
__device__ __forceinline__ void cp16(uint32_t dst, const void* src) {
    asm volatile("cp.async.cg.shared.global [%0], [%1], 16;" :: "r"(dst), "l"(src));
}
#define CP_COMMIT() asm volatile("cp.async.commit_group;" ::: "memory")
#define CP_WAIT(n)  asm volatile("cp.async.wait_group %0;" :: "n"(n) : "memory")
__device__ __forceinline__ void ldm_x4(uint32_t* r, uint32_t a) {
    asm volatile("ldmatrix.sync.aligned.m8n8.x4.shared.b16 {%0,%1,%2,%3}, [%4];"
        : "=r"(r[0]), "=r"(r[1]), "=r"(r[2]), "=r"(r[3]) : "r"(a));
}
__device__ __forceinline__ void ldm_x4t(uint32_t* r, uint32_t a) {
    asm volatile("ldmatrix.sync.aligned.m8n8.x4.trans.shared.b16 {%0,%1,%2,%3}, [%4];"
        : "=r"(r[0]), "=r"(r[1]), "=r"(r[2]), "=r"(r[3]) : "r"(a));
}

#define TST  40    // smem row stride (elements) for 32-wide tiles

// ======================= scratch (device globals) =======================
__device__ __nv_bfloat16 g_qb[B_*H_*S_*DH_];
__device__ __nv_bfloat16 g_kb[B_*H_*S_*DH_];
__device__ __nv_bfloat16 g_vb[B_*H_*S_*DH_];
__device__ __nv_bfloat16 g_attnb[M_*D_];
__device__ __nv_bfloat16 g_hb[M_*D_];
__device__ float         g_h[M_*D_];
__device__ __nv_bfloat16 g_ffb[(size_t)M_*FF_];
__device__ __nv_bfloat16 g_wip[L_*3*D_*D_];
__device__ __nv_bfloat16 g_wout[L_*D_*D_];
__device__ __nv_bfloat16 g_wf1[L_*FF_*D_];
__device__ __nv_bfloat16 g_wf2[L_*D_*FF_];

// ======================= fp32 -> bf16 conversion =======================
__global__ __launch_bounds__(256) void cvt_kernel(const float* __restrict__ s,
                                                  __nv_bfloat16* __restrict__ d, int n) {
    int i = (blockIdx.x * 256 + threadIdx.x) * 4;
    if (i < n) {
        float4 v = *reinterpret_cast<const float4*>(s + i);
        *reinterpret_cast<uint2*>(d + i) = make_uint2(packbf2(v.x, v.y), packbf2(v.z, v.w));
    }
}

// ======================= pipelined bf16 MMA GEMM (3-stage) =======================
// (unchanged from R7 — protected)
#define MM_SMEM 67072
template<int EPI>
__global__ __launch_bounds__(256)
void mm_kernel(const __nv_bfloat16* __restrict__ A, const __nv_bfloat16* __restrict__ W,
               const float* __restrict__ bias, const float* __restrict__ R,
               const float* __restrict__ lng, const float* __restrict__ lnb,
               float* __restrict__ outF, __nv_bfloat16* __restrict__ outB,
               __nv_bfloat16* __restrict__ qo, __nv_bfloat16* __restrict__ ko,
               __nv_bfloat16* __restrict__ vo, int Nstride, int K)
{
    extern __shared__ char smx[];
    const uint32_t sbase = cvta_s(smx);
    float* bias_s = (float*)(smx + 61440);
    float* lng_s  = (float*)(smx + 61952);
    float* lnb_s  = (float*)(smx + 62464);
    float (*redS)[4] = (float(*)[4])(smx + 62976);
    float (*redQ)[4] = (float(*)[4])(smx + 65024);

    const int t    = threadIdx.x;
    const int wid  = t >> 5;
    const int lane = t & 31;
    const int g    = lane >> 2;
    const int tq   = lane & 3;
    const int wm   = wid >> 2;
    const int wn   = wid & 3;
    const int row0 = blockIdx.y * 128;
    const int n0   = blockIdx.x * 128;

    if (t < 128) {
        bias_s[t] = bias[n0 + t];
        if (EPI == 2) { lng_s[t] = lng[t]; lnb_s[t] = lnb[t]; }
    }

    auto sA = [&](int s) -> uint32_t { return sbase + s * 10240; };
    auto sB = [&](int s) -> uint32_t { return sbase + 30720 + s * 10240; };

    auto load_tile = [&](int kt, int stg) {
        const int k0 = kt << 5;
#pragma unroll
        for (int i = 0; i < 2; i++) {
            int id = t + (i << 8);
            int r = id >> 2, qq = id & 3;
            cp16(sA(stg) + r * (TST*2) + qq * 16, &A[(size_t)(row0 + r) * K + k0 + qq * 8]);
            cp16(sB(stg) + r * (TST*2) + qq * 16, &W[(size_t)(n0   + r) * K + k0 + qq * 8]);
        }
    };

    float acc[4][4][4];
#pragma unroll
    for (int mf = 0; mf < 4; mf++)
#pragma unroll
        for (int nf = 0; nf < 4; nf++)
#pragma unroll
            for (int e = 0; e < 4; e++) acc[mf][nf][e] = 0.f;

    const int nkt = K >> 5;
    load_tile(0, 0); CP_COMMIT();
    if (nkt > 1) { load_tile(1, 1); CP_COMMIT(); }

    const int aRow = wm * 64 + (lane & 15);
    const int aColX = (lane >> 4) * 8;
    const int bRow = wn * 32 + (lane & 7) + ((lane >> 4) << 3);
    const int bColX = ((lane >> 3) & 1) * 8;

    for (int kt = 0; kt < nkt; kt++) {
        const int stg = kt % 3;
        if (kt < nkt - 1) CP_WAIT(1); else CP_WAIT(0);
        __syncthreads();
        if (kt + 2 < nkt) { load_tile(kt + 2, (kt + 2) % 3); CP_COMMIT(); }

#pragma unroll
        for (int ks = 0; ks < 2; ks++) {
            const int kk = ks << 4;
            uint32_t af[4][4];
#pragma unroll
            for (int mf = 0; mf < 4; mf++)
                ldm_x4(af[mf], sA(stg) + ((aRow + mf * 16) * TST + kk + aColX) * 2);
            uint32_t bf[4][2];
#pragma unroll
            for (int pp = 0; pp < 2; pp++) {
                uint32_t r4[4];
                ldm_x4(r4, sB(stg) + ((bRow + pp * 16) * TST + kk + bColX) * 2);
                bf[pp*2][0] = r4[0]; bf[pp*2][1] = r4[1];
                bf[pp*2+1][0] = r4[2]; bf[pp*2+1][1] = r4[3];
            }
#pragma unroll
            for (int mf = 0; mf < 4; mf++)
#pragma unroll
                for (int nf = 0; nf < 4; nf++)
                    mma16816(acc[mf][nf], af[mf], bf[nf]);
        }
    }

    // ---- epilogue ----
    if (EPI == 2) {
#pragma unroll
        for (int mf = 0; mf < 4; mf++) {
            const int m0 = row0 + wm * 64 + mf * 16 + g;
            const int m1 = m0 + 8;
            float s0 = 0.f, q0 = 0.f, s1 = 0.f, q1 = 0.f;
#pragma unroll
            for (int nf = 0; nf < 4; nf++) {
                const int c = wn * 32 + nf * 8 + tq * 2;
                float2 r0 = *reinterpret_cast<const float2*>(R + (size_t)m0 * 128 + c);
                float2 r1 = *reinterpret_cast<const float2*>(R + (size_t)m1 * 128 + c);
                float v0 = acc[mf][nf][0] + bias_s[c]     + r0.x;
                float v1 = acc[mf][nf][1] + bias_s[c + 1] + r0.y;
                float v2 = acc[mf][nf][2] + bias_s[c]     + r1.x;
                float v3 = acc[mf][nf][3] + bias_s[c + 1] + r1.y;
                acc[mf][nf][0] = v0; acc[mf][nf][1] = v1;
                acc[mf][nf][2] = v2; acc[mf][nf][3] = v3;
                s0 += v0 + v1; q0 += v0*v0 + v1*v1;
                s1 += v2 + v3; q1 += v2*v2 + v3*v3;
            }
            s0 += __shfl_xor_sync(0xffffffffu, s0, 1); s0 += __shfl_xor_sync(0xffffffffu, s0, 2);
            q0 += __shfl_xor_sync(0xffffffffu, q0, 1); q0 += __shfl_xor_sync(0xffffffffu, q0, 2);
            s1 += __shfl_xor_sync(0xffffffffu, s1, 1); s1 += __shfl_xor_sync(0xffffffffu, s1, 2);
            q1 += __shfl_xor_sync(0xffffffffu, q1, 1); q1 += __shfl_xor_sync(0xffffffffu, q1, 2);
            if (tq == 0) {
                const int rl = wm * 64 + mf * 16 + g;
                redS[rl][wn] = s0; redQ[rl][wn] = q0;
                redS[rl + 8][wn] = s1; redQ[rl + 8][wn] = q1;
            }
        }
        __syncthreads();
#pragma unroll
        for (int mf = 0; mf < 4; mf++) {
            const int rl = wm * 64 + mf * 16 + g;
            const int m0 = row0 + rl, m1 = m0 + 8;
            float sum0 = redS[rl][0] + redS[rl][1] + redS[rl][2] + redS[rl][3];
            float sq0  = redQ[rl][0] + redQ[rl][1] + redQ[rl][2] + redQ[rl][3];
            float sum1 = redS[rl+8][0] + redS[rl+8][1] + redS[rl+8][2] + redS[rl+8][3];
            float sq1  = redQ[rl+8][0] + redQ[rl+8][1] + redQ[rl+8][2] + redQ[rl+8][3];
            float mean0 = sum0 * (1.f/128.f);
            float mean1 = sum1 * (1.f/128.f);
            float rstd0 = rsqrtf(sq0 * (1.f/128.f) - mean0*mean0 + 1e-5f);
            float rstd1 = rsqrtf(sq1 * (1.f/128.f) - mean1*mean1 + 1e-5f);
#pragma unroll
            for (int nf = 0; nf < 4; nf++) {
                const int c = wn * 32 + nf * 8 + tq * 2;
                float y0 = (acc[mf][nf][0] - mean0) * rstd0 * lng_s[c]   + lnb_s[c];
                float y1 = (acc[mf][nf][1] - mean0) * rstd0 * lng_s[c+1] + lnb_s[c+1];
                float y2 = (acc[mf][nf][2] - mean1) * rstd1 * lng_s[c]   + lnb_s[c];
                float y3 = (acc[mf][nf][3] - mean1) * rstd1 * lng_s[c+1] + lnb_s[c+1];
                *reinterpret_cast<float2*>(outF + (size_t)m0 * 128 + c) = make_float2(y0, y1);
                *reinterpret_cast<float2*>(outF + (size_t)m1 * 128 + c) = make_float2(y2, y3);
                *reinterpret_cast<uint32_t*>(outB + (size_t)m0 * 128 + c) = packbf2(y0, y1);
                *reinterpret_cast<uint32_t*>(outB + (size_t)m1 * 128 + c) = packbf2(y2, y3);
            }
        }
    } else {
#pragma unroll
        for (int mf = 0; mf < 4; mf++) {
            const int m0 = row0 + wm * 64 + mf * 16 + g;
            const int m1 = m0 + 8;
#pragma unroll
            for (int nf = 0; nf < 4; nf++) {
                const int c = wn * 32 + nf * 8 + tq * 2;
                float v0 = acc[mf][nf][0] + bias_s[c];
                float v1 = acc[mf][nf][1] + bias_s[c + 1];
                float v2 = acc[mf][nf][2] + bias_s[c];
                float v3 = acc[mf][nf][3] + bias_s[c + 1];
                if (EPI == 0) {
                    __nv_bfloat16* dst = (blockIdx.x == 0) ? qo : ((blockIdx.x == 1) ? ko : vo);
                    if (blockIdx.x == 0) { v0 *= QSCALE; v1 *= QSCALE; v2 *= QSCALE; v3 *= QSCALE; }
                    const int hh = c >> 5, dd = c & 31;
                    int b0i = m0 >> 11, s0i = m0 & 2047;
                    int b1i = m1 >> 11, s1i = m1 & 2047;
                    *reinterpret_cast<uint32_t*>(dst + ((size_t)(b0i * H_ + hh) * S_ + s0i) * DH_ + dd) = packbf2(v0, v1);
                    *reinterpret_cast<uint32_t*>(dst + ((size_t)(b1i * H_ + hh) * S_ + s1i) * DH_ + dd) = packbf2(v2, v3);
                } else {
                    *reinterpret_cast<uint32_t*>(outB + (size_t)m0 * Nstride + n0 + c) =
                        packbf2(fmaxf(v0, 0.f), fmaxf(v1, 0.f));
                    *reinterpret_cast<uint32_t*>(outB + (size_t)m1 * Nstride + n0 + c) =
                        packbf2(fmaxf(v2, 0.f), fmaxf(v3, 0.f));
                }
            }
        }
    }
}

// ======================= pipelined MMA flash attention (3-stage, split-key warps) =======================
// CTA: (bh, 128 queries), 256 threads. Warp = (key-half, query-group): 32q x 32k tile.
// Each K/V ldmatrix fragment feeds 4 MMAs (2 m-tiles) -> half the L1 traffic of R7.
// O and l are partial per key-half; reduced via smem at the end.
// smem: Qs@0 (10240), stage s: K@10240+s*10240, V@15360+s*10240 (total 40960).
// End-of-kernel reuse: Opart@0 (16896 = 4*32*33*4), Lsm@16896 (1024).
#define AT_SMEM 40960
#define NKV (S_ >> 6)
__global__ __launch_bounds__(256)
void attn_kernel(const __nv_bfloat16* __restrict__ q, const __nv_bfloat16* __restrict__ k,
                 const __nv_bfloat16* __restrict__ v, __nv_bfloat16* __restrict__ out)
{
    extern __shared__ char smx[];
    const uint32_t sbase = cvta_s(smx);
    const uint32_t sQ = sbase;

    const int t    = threadIdx.x;
    const int wid  = t >> 5;
    const int lane = t & 31;
    const int g    = lane >> 2;
    const int tq   = lane & 3;
    const int half = wid >> 2;      // key half (0: keys 0-31, 1: keys 32-63 of tile)
    const int wq   = wid & 3;       // query group (32 queries each)
    const int bh   = blockIdx.y, b = bh >> 2, h = bh & 3;
    const int q0   = blockIdx.x * 128;

    auto sK = [&](int s) -> uint32_t { return sbase + 10240 + s * 10240; };
    auto sV = [&](int s) -> uint32_t { return sbase + 15360 + s * 10240; };

    auto load_kv = [&](int tile, int stg) {
        const int j0 = tile << 6;
        int r = t >> 2, qq = t & 3;
        cp16(sK(stg) + r * (TST*2) + qq * 16, &k[((size_t)bh * S_ + j0 + r) * DH_ + qq * 8]);
        cp16(sV(stg) + r * (TST*2) + qq * 16, &v[((size_t)bh * S_ + j0 + r) * DH_ + qq * 8]);
    };

    // prologue: Q + KV0, then KV1
#pragma unroll
    for (int i = 0; i < 2; i++) {
        int id = t + (i << 8);
        int r = id >> 2, qq = id & 3;
        cp16(sQ + r * (TST*2) + qq * 16, &q[((size_t)bh * S_ + q0 + r) * DH_ + qq * 8]);
    }
    load_kv(0, 0);
    CP_COMMIT();
    load_kv(1, 1);
    CP_COMMIT();

    float o[2][4][4];
    float lgA[2] = {0.f, 0.f}, lgB[2] = {0.f, 0.f};  // [mt]: rows g / g+8
#pragma unroll
    for (int mt = 0; mt < 2; mt++)
#pragma unroll
        for (int nf = 0; nf < 4; nf++)
#pragma unroll
            for (int e = 0; e < 4; e++) o[mt][nf][e] = 0.f;

    uint32_t af[2][2][4];   // [mt][ks]

    const int aColX = (lane >> 4) * 8;
    const int bRow = (lane & 7) + ((lane >> 4) << 3);
    const int bColX = ((lane >> 3) & 1) * 8;
    const int vRow = (lane & 7) + (((lane >> 3) & 1) << 3);
    const int vColX = (lane >> 4) * 8;

    for (int it = 0; it < NKV; it++) {
        const int stg = it % 3;
        if (it < NKV - 1) CP_WAIT(1); else CP_WAIT(0);
        __syncthreads();
        if (it + 2 < NKV) { load_kv(it + 2, (it + 2) % 3); CP_COMMIT(); }

        if (it == 0) {
#pragma unroll
            for (int mt = 0; mt < 2; mt++)
#pragma unroll
                for (int ks = 0; ks < 2; ks++)
                    ldm_x4(af[mt][ks],
                        sQ + ((wq * 32 + mt * 16 + (lane & 15)) * TST + ks * 16 + aColX) * 2);
        }

        // S[32q x 32k] = Q @ K^T   (K frags shared across both m-tiles)
        float sc[2][4][4];
#pragma unroll
        for (int mt = 0; mt < 2; mt++)
#pragma unroll
            for (int nf = 0; nf < 4; nf++)
#pragma unroll
                for (int e = 0; e < 4; e++) sc[mt][nf][e] = 0.f;
#pragma unroll
        for (int ks = 0; ks < 2; ks++) {
            const int kk = ks << 4;
#pragma unroll
            for (int pp = 0; pp < 2; pp++) {
                uint32_t r4[4];
                ldm_x4(r4, sK(stg) + ((half * 32 + pp * 16 + bRow) * TST + kk + bColX) * 2);
                uint32_t b0[2] = { r4[0], r4[1] }, b1[2] = { r4[2], r4[3] };
#pragma unroll
                for (int mt = 0; mt < 2; mt++) {
                    mma16816(sc[mt][pp*2],   af[mt][ks], b0);
                    mma16816(sc[mt][pp*2+1], af[mt][ks], b1);
                }
            }
        }

        // p = ex2(s); accumulate partial l; pack PV A-frags
        uint32_t pb[2][4][2];
#pragma unroll
        for (int mt = 0; mt < 2; mt++)
#pragma unroll
            for (int nf = 0; nf < 4; nf++) {
                float p0 = ex2f(sc[mt][nf][0]);
                float p1 = ex2f(sc[mt][nf][1]);
                float p2 = ex2f(sc[mt][nf][2]);
                float p3 = ex2f(sc[mt][nf][3]);
                lgA[mt] += p0 + p1;
                lgB[mt] += p2 + p3;
                pb[mt][nf][0] = packbf2(p0, p1);
                pb[mt][nf][1] = packbf2(p2, p3);
            }

        // O += P @ V  (V frags shared across both m-tiles)
#pragma unroll
        for (int kf = 0; kf < 2; kf++) {
            uint32_t a4[2][4];
#pragma unroll
            for (int mt = 0; mt < 2; mt++) {
                a4[mt][0] = pb[mt][2*kf][0];   a4[mt][1] = pb[mt][2*kf][1];
                a4[mt][2] = pb[mt][2*kf+1][0]; a4[mt][3] = pb[mt][2*kf+1][1];
            }
#pragma unroll
            for (int pp = 0; pp < 2; pp++) {
                uint32_t r4[4];
                ldm_x4t(r4, sV(stg) + ((half * 32 + kf * 16 + vRow) * TST + pp * 16 + vColX) * 2);
                uint32_t b0[2] = { r4[0], r4[1] }, b1[2] = { r4[2], r4[3] };
#pragma unroll
                for (int mt = 0; mt < 2; mt++) {
                    mma16816(o[mt][pp*2],   a4[mt], b0);
                    mma16816(o[mt][pp*2+1], a4[mt], b1);
                }
            }
        }
    }

    // ---- cross-half reduction of O and l ----
    __syncthreads();   // all warps done with KV smem

    float* Osm = (float*)smx;                 // [wq][lane][33-padded 32 floats]
    float* Lsm = (float*)(smx + 16896);       // idx(half,wq,mt,hi,g)

#pragma unroll
    for (int mt = 0; mt < 2; mt++) {
        lgA[mt] += __shfl_xor_sync(0xffffffffu, lgA[mt], 1);
        lgA[mt] += __shfl_xor_sync(0xffffffffu, lgA[mt], 2);
        lgB[mt] += __shfl_xor_sync(0xffffffffu, lgB[mt], 1);
        lgB[mt] += __shfl_xor_sync(0xffffffffu, lgB[mt], 2);
    }

    if (half == 1) {
        float* dst = Osm + (wq * 32 + lane) * 33;
#pragma unroll
        for (int mt = 0; mt < 2; mt++)
#pragma unroll
            for (int nf = 0; nf < 4; nf++)
#pragma unroll
                for (int e = 0; e < 4; e++)
                    dst[mt * 16 + nf * 4 + e] = o[mt][nf][e];
    }
    if (tq == 0) {
#pragma unroll
        for (int mt = 0; mt < 2; mt++) {
            Lsm[(((half * 4 + wq) * 2 + mt) * 2 + 0) * 8 + g] = lgA[mt];
            Lsm[(((half * 4 + wq) * 2 + mt) * 2 + 1) * 8 + g] = lgB[mt];
        }
    }
    __syncthreads();

    if (half == 0) {
        const float* src = Osm + (wq * 32 + lane) * 33;
#pragma unroll
        for (int mt = 0; mt < 2; mt++) {
            float ltot0 = lgA[mt] + Lsm[(((4 + wq) * 2 + mt) * 2 + 0) * 8 + g];
            float ltot1 = lgB[mt] + Lsm[(((4 + wq) * 2 + mt) * 2 + 1) * 8 + g];
            const float inv0 = 1.f / ltot0;
            const float inv1 = 1.f / ltot1;
            const int r0 = q0 + wq * 32 + mt * 16 + g;
            const int r1 = r0 + 8;
#pragma unroll
            for (int nf = 0; nf < 4; nf++) {
                const int dd = nf * 8 + tq * 2;
                float o0 = o[mt][nf][0] + src[mt * 16 + nf * 4 + 0];
                float o1 = o[mt][nf][1] + src[mt * 16 + nf * 4 + 1];
                float o2 = o[mt][nf][2] + src[mt * 16 + nf * 4 + 2];
                float o3 = o[mt][nf][3] + src[mt * 16 + nf * 4 + 3];
                *reinterpret_cast<uint32_t*>(out + ((size_t)(b * S_ + r0)) * D_ + h * DH_ + dd) =
                    packbf2(o0 * inv0, o1 * inv0);
                *reinterpret_cast<uint32_t*>(out + ((size_t)(b * S_ + r1)) * D_ + h * DH_ + dd) =
                    packbf2(o2 * inv1, o3 * inv1);
            }
        }
    }
}

// ======================= Head: FC -> softmax -> rebalance =======================
__global__ __launch_bounds__(512)
void head_kernel(const float* __restrict__ hbuf, const float* __restrict__ fcw,
                 const float* __restrict__ fcb, float* __restrict__ out)
{
    __shared__ float logits[B_][OUT_];
    const int t = threadIdx.x;
    if (t < B_ * OUT_) {
        int b = t / OUT_;
        int o = t % OUT_;
        const float* hr = hbuf + ((size_t)(b * S_ + (S_ - 1))) * D_;
        float acc = fcb[o];
        for (int d = 0; d < D_; d++) acc += hr[d] * fcw[o * D_ + d];
        logits[b][o] = acc;
    }
    __syncthreads();
    if (t < B_) {
        const float UB = 0.3f, LB = 0.0f;
        float wv[OUT_], old[OUT_], wc[OUT_], res[OUT_];
        float mx = -1e30f;
        for (int o = 0; o < OUT_; o++) mx = fmaxf(mx, logits[t][o]);
        float sum = 0.f;
        for (int o = 0; o < OUT_; o++) { wv[o] = expf(logits[t][o] - mx); sum += wv[o]; }
        float inv = 1.f / sum;
        for (int o = 0; o < OUT_; o++) wv[o] *= inv;
        bool done = false;
        for (int o = 0; o < OUT_; o++) {
            old[o] = wv[o];
            wc[o]  = fminf(fmaxf(wv[o], LB), UB);
            res[o] = wv[o];
        }
        for (int it = 0; it < 16; it++) {
            float leftover = 0.f;
            for (int o = 0; o < OUT_; o++) leftover += old[o] - wc[o];
            float denom = 0.f;
            float noms[OUT_];
            for (int o = 0; o < OUT_; o++) {
                noms[o] = (wc[o] != UB) ? wc[o] : 0.f;
                denom += noms[o];
            }
            if (denom == 0.f) denom = 1.f;
            float cand[OUT_];
            bool any = false;
            for (int o = 0; o < OUT_; o++) {
                cand[o] = wc[o] + leftover * noms[o] / denom;
                if (cand[o] > UB) any = true;
            }
            if (!done)
                for (int o = 0; o < OUT_; o++) res[o] = cand[o];
            done = done || !any;
            if (!done) {
                for (int o = 0; o < OUT_; o++) {
                    old[o] = cand[o];
                    wc[o]  = fminf(fmaxf(cand[o], LB), UB);
                }
            }
        }
        for (int o = 0; o < OUT_; o++) out[t * OUT_ + o] = res[o];
    }
}

// ======================= launch =======================
extern "C" void kernel_launch(void* const* d_in, const int* in_sizes, int n_in,
                              void* d_out, int out_size)
{
    const float* x   = (const float*)d_in[0];
    const float* ipw = (const float*)d_in[1];
    const float* ipb = (const float*)d_in[2];
    const float* ow  = (const float*)d_in[3];
    const float* ob  = (const float*)d_in[4];
    const float* l1g = (const float*)d_in[5];
    const float* l1b = (const float*)d_in[6];
    const float* f1w = (const float*)d_in[7];
    const float* f1b = (const float*)d_in[8];
    const float* f2w = (const float*)d_in[9];
    const float* f2b = (const float*)d_in[10];
    const float* l2g = (const float*)d_in[11];
    const float* l2b = (const float*)d_in[12];
    const float* fcw = (const float*)d_in[13];
    const float* fcb = (const float*)d_in[14];

    __nv_bfloat16 *qb, *kb, *vb, *attnb, *hb, *ffb, *wip, *wout, *wf1, *wf2;
    float *h;
    cudaGetSymbolAddress((void**)&qb,    g_qb);
    cudaGetSymbolAddress((void**)&kb,    g_kb);
    cudaGetSymbolAddress((void**)&vb,    g_vb);
    cudaGetSymbolAddress((void**)&attnb, g_attnb);
    cudaGetSymbolAddress((void**)&hb,    g_hb);
    cudaGetSymbolAddress((void**)&h,     g_h);
    cudaGetSymbolAddress((void**)&ffb,   g_ffb);
    cudaGetSymbolAddress((void**)&wip,   g_wip);
    cudaGetSymbolAddress((void**)&wout,  g_wout);
    cudaGetSymbolAddress((void**)&wf1,   g_wf1);
    cudaGetSymbolAddress((void**)&wf2,   g_wf2);

    cudaFuncSetAttribute(mm_kernel<0>, cudaFuncAttributeMaxDynamicSharedMemorySize, MM_SMEM);
    cudaFuncSetAttribute(mm_kernel<1>, cudaFuncAttributeMaxDynamicSharedMemorySize, MM_SMEM);
    cudaFuncSetAttribute(mm_kernel<2>, cudaFuncAttributeMaxDynamicSharedMemorySize, MM_SMEM);
    cudaFuncSetAttribute(attn_kernel,  cudaFuncAttributeMaxDynamicSharedMemorySize, AT_SMEM);

    cvt_kernel<<<(L_*3*D_*D_)/1024, 256>>>(ipw, wip, L_*3*D_*D_);   // launch 0
    cvt_kernel<<<(M_*D_)/1024,      256>>>(x,   hb,  M_*D_);        // launch 1

    for (int l = 0; l < L_; l++) {
        const float* hinF = (l == 0) ? x : h;

        // QKV projection -> q/k/v bf16 [b,h,s,32] (q pre-scaled)
        mm_kernel<0><<<dim3(3, M_/128), 256, MM_SMEM>>>(
            hb, wip + (size_t)l*3*D_*D_, ipb + (size_t)l*3*D_,
            nullptr, nullptr, nullptr, nullptr, nullptr, qb, kb, vb, 3*D_, D_);

        // flash attention
        attn_kernel<<<dim3(S_/128, B_*H_), 256, AT_SMEM>>>(qb, kb, vb, attnb);

        if (l == 0) cvt_kernel<<<(L_*D_*D_)/1024, 256>>>(ow, wout, L_*D_*D_);

        // out projection + residual + LN1 -> h, hb
        mm_kernel<2><<<dim3(1, M_/128), 256, MM_SMEM>>>(
            attnb, wout + (size_t)l*D_*D_, ob + (size_t)l*D_,
            hinF, l1g + (size_t)l*D_, l1b + (size_t)l*D_,
            h, hb, nullptr, nullptr, nullptr, D_, D_);

        if (l == 0) cvt_kernel<<<(L_*FF_*D_)/1024, 256>>>(f1w, wf1, L_*FF_*D_);

        // FF1 + relu -> ffb (bf16)
        mm_kernel<1><<<dim3(FF_/128, M_/128), 256, MM_SMEM>>>(
            hb, wf1 + (size_t)l*FF_*D_, f1b + (size_t)l*FF_,
            nullptr, nullptr, nullptr, nullptr, ffb, nullptr, nullptr, nullptr, FF_, D_);

        if (l == 0) cvt_kernel<<<(L_*D_*FF_)/1024, 256>>>(f2w, wf2, L_*D_*FF_);

        // FF2 + residual(h) + LN2 -> h, hb
        mm_kernel<2><<<dim3(1, M_/128), 256, MM_SMEM>>>(
            ffb, wf2 + (size_t)l*D_*FF_, f2b + (size_t)l*D_,
            h, l2g + (size_t)l*D_, l2b + (size_t)l*D_,
            h, hb, nullptr, nullptr, nullptr, D_, FF_);
    }

    head_kernel<<<1, 512>>>(h, fcw, fcb, (float*)d_out);
}

// round 9
// speedup vs baseline: 1.0185x; 1.0185x over previous
#include <cuda_runtime.h>
#include <cuda_bf16.h>
#include <cstdint>
#include <math.h>

#define B_   16
#define S_   2048
#define D_   128
#define H_   4
#define DH_  32
#define FF_  512
#define L_   4
#define OUT_ 30
#define M_   (B_*S_)   // 32768

// log2(e) / sqrt(32): folded into Q so softmax is a bare ex2
#define QSCALE 0.25506626866f

// ======================= low-level helpers =======================
__device__ __forceinline__ void mma16816(float* d, const uint32_t* a, const uint32_t* b) {
    asm volatile("mma.sync.aligned.m16n8k16.row.col.f32.bf16.bf16.f32 "
        "{%0,%1,%2,%3}, {%4,%5,%6,%7}, {%8,%9}, {%0,%1,%2,%3};"
        : "+f"(d[0]), "+f"(d[1]), "+f"(d[2]), "+f"(d[3])
        : "r"(a[0]), "r"(a[1]), "r"(a[2]), "r"(a[3]), "r"(b[0]), "r"(b[1]));
}
__device__ __forceinline__ uint32_t packbf2(float x, float y) {
    __nv_bfloat162 p = __floats2bfloat162_rn(x, y);
    return *(uint32_t*)&p;
}
__device__ __forceinline__ float ex2f(float x) {
    float y; asm("ex2.approx.f32 %0, %1;" : "=f"(y) : "f"(x)); return y;
}
__device__ __forceinline__ uint32_t cvta_s(const void* p) {
    return (uint32_t)__cvta_generic_to_shared(p);
}
__device__ __forceinline__ void cp16(uint32_t dst, const void* src) {
    asm volatile("cp.async.cg.shared.global [%0], [%1], 16;" :: "r"(dst), "l"(src));
}
#define CP_COMMIT() asm volatile("cp.async.commit_group;" ::: "memory")
#define CP_WAIT(n)  asm volatile("cp.async.wait_group %0;" :: "n"(n) : "memory")
__device__ __forceinline__ void ldm_x4(uint32_t* r, uint32_t a) {
    asm volatile("ldmatrix.sync.aligned.m8n8.x4.shared.b16 {%0,%1,%2,%3}, [%4];"
        : "=r"(r[0]), "=r"(r[1]), "=r"(r[2]), "=r"(r[3]) : "r"(a));
}
__device__ __forceinline__ void ldm_x4t(uint32_t* r, uint32_t a) {
    asm volatile("ldmatrix.sync.aligned.m8n8.x4.trans.shared.b16 {%0,%1,%2,%3}, [%4];"
        : "=r"(r[0]), "=r"(r[1]), "=r"(r[2]), "=r"(r[3]) : "r"(a));
}

#define TST  40    // smem row stride (elements) for 32-wide tiles

// ======================= scratch (device globals) =======================
__device__ __nv_bfloat16 g_qb[B_*H_*S_*DH_];
__device__ __nv_bfloat16 g_kb[B_*H_*S_*DH_];
__device__ __nv_bfloat16 g_vb[B_*H_*S_*DH_];
__device__ __nv_bfloat16 g_attnb[M_*D_];
__device__ __nv_bfloat16 g_hb[M_*D_];
__device__ float         g_h[M_*D_];
__device__ __nv_bfloat16 g_ffb[(size_t)M_*FF_];
__device__ __nv_bfloat16 g_wip[L_*3*D_*D_];
__device__ __nv_bfloat16 g_wout[L_*D_*D_];
__device__ __nv_bfloat16 g_wf1[L_*FF_*D_];
__device__ __nv_bfloat16 g_wf2[L_*D_*FF_];

// ======================= fp32 -> bf16 conversion =======================
__global__ __launch_bounds__(256) void cvt_kernel(const float* __restrict__ s,
                                                  __nv_bfloat16* __restrict__ d, int n) {
    int i = (blockIdx.x * 256 + threadIdx.x) * 4;
    if (i < n) {
        float4 v = *reinterpret_cast<const float4*>(s + i);
        *reinterpret_cast<uint2*>(d + i) = make_uint2(packbf2(v.x, v.y), packbf2(v.z, v.w));
    }
}

// ======================= pipelined bf16 MMA GEMM (3-stage) =======================
// (unchanged from R7 — protected)
#define MM_SMEM 67072
template<int EPI>
__global__ __launch_bounds__(256)
void mm_kernel(const __nv_bfloat16* __restrict__ A, const __nv_bfloat16* __restrict__ W,
               const float* __restrict__ bias, const float* __restrict__ R,
               const float* __restrict__ lng, const float* __restrict__ lnb,
               float* __restrict__ outF, __nv_bfloat16* __restrict__ outB,
               __nv_bfloat16* __restrict__ qo, __nv_bfloat16* __restrict__ ko,
               __nv_bfloat16* __restrict__ vo, int Nstride, int K)
{
    extern __shared__ char smx[];
    const uint32_t sbase = cvta_s(smx);
    float* bias_s = (float*)(smx + 61440);
    float* lng_s  = (float*)(smx + 61952);
    float* lnb_s  = (float*)(smx + 62464);
    float (*redS)[4] = (float(*)[4])(smx + 62976);
    float (*redQ)[4] = (float(*)[4])(smx + 65024);

    const int t    = threadIdx.x;
    const int wid  = t >> 5;
    const int lane = t & 31;
    const int g    = lane >> 2;
    const int tq   = lane & 3;
    const int wm   = wid >> 2;
    const int wn   = wid & 3;
    const int row0 = blockIdx.y * 128;
    const int n0   = blockIdx.x * 128;

    if (t < 128) {
        bias_s[t] = bias[n0 + t];
        if (EPI == 2) { lng_s[t] = lng[t]; lnb_s[t] = lnb[t]; }
    }

    auto sA = [&](int s) -> uint32_t { return sbase + s * 10240; };
    auto sB = [&](int s) -> uint32_t { return sbase + 30720 + s * 10240; };

    auto load_tile = [&](int kt, int stg) {
        const int k0 = kt << 5;
#pragma unroll
        for (int i = 0; i < 2; i++) {
            int id = t + (i << 8);
            int r = id >> 2, qq = id & 3;
            cp16(sA(stg) + r * (TST*2) + qq * 16, &A[(size_t)(row0 + r) * K + k0 + qq * 8]);
            cp16(sB(stg) + r * (TST*2) + qq * 16, &W[(size_t)(n0   + r) * K + k0 + qq * 8]);
        }
    };

    float acc[4][4][4];
#pragma unroll
    for (int mf = 0; mf < 4; mf++)
#pragma unroll
        for (int nf = 0; nf < 4; nf++)
#pragma unroll
            for (int e = 0; e < 4; e++) acc[mf][nf][e] = 0.f;

    const int nkt = K >> 5;
    load_tile(0, 0); CP_COMMIT();
    if (nkt > 1) { load_tile(1, 1); CP_COMMIT(); }

    const int aRow = wm * 64 + (lane & 15);
    const int aColX = (lane >> 4) * 8;
    const int bRow = wn * 32 + (lane & 7) + ((lane >> 4) << 3);
    const int bColX = ((lane >> 3) & 1) * 8;

    for (int kt = 0; kt < nkt; kt++) {
        const int stg = kt % 3;
        if (kt < nkt - 1) CP_WAIT(1); else CP_WAIT(0);
        __syncthreads();
        if (kt + 2 < nkt) { load_tile(kt + 2, (kt + 2) % 3); CP_COMMIT(); }

#pragma unroll
        for (int ks = 0; ks < 2; ks++) {
            const int kk = ks << 4;
            uint32_t af[4][4];
#pragma unroll
            for (int mf = 0; mf < 4; mf++)
                ldm_x4(af[mf], sA(stg) + ((aRow + mf * 16) * TST + kk + aColX) * 2);
            uint32_t bf[4][2];
#pragma unroll
            for (int pp = 0; pp < 2; pp++) {
                uint32_t r4[4];
                ldm_x4(r4, sB(stg) + ((bRow + pp * 16) * TST + kk + bColX) * 2);
                bf[pp*2][0] = r4[0]; bf[pp*2][1] = r4[1];
                bf[pp*2+1][0] = r4[2]; bf[pp*2+1][1] = r4[3];
            }
#pragma unroll
            for (int mf = 0; mf < 4; mf++)
#pragma unroll
                for (int nf = 0; nf < 4; nf++)
                    mma16816(acc[mf][nf], af[mf], bf[nf]);
        }
    }

    // ---- epilogue ----
    if (EPI == 2) {
#pragma unroll
        for (int mf = 0; mf < 4; mf++) {
            const int m0 = row0 + wm * 64 + mf * 16 + g;
            const int m1 = m0 + 8;
            float s0 = 0.f, q0 = 0.f, s1 = 0.f, q1 = 0.f;
#pragma unroll
            for (int nf = 0; nf < 4; nf++) {
                const int c = wn * 32 + nf * 8 + tq * 2;
                float2 r0 = *reinterpret_cast<const float2*>(R + (size_t)m0 * 128 + c);
                float2 r1 = *reinterpret_cast<const float2*>(R + (size_t)m1 * 128 + c);
                float v0 = acc[mf][nf][0] + bias_s[c]     + r0.x;
                float v1 = acc[mf][nf][1] + bias_s[c + 1] + r0.y;
                float v2 = acc[mf][nf][2] + bias_s[c]     + r1.x;
                float v3 = acc[mf][nf][3] + bias_s[c + 1] + r1.y;
                acc[mf][nf][0] = v0; acc[mf][nf][1] = v1;
                acc[mf][nf][2] = v2; acc[mf][nf][3] = v3;
                s0 += v0 + v1; q0 += v0*v0 + v1*v1;
                s1 += v2 + v3; q1 += v2*v2 + v3*v3;
            }
            s0 += __shfl_xor_sync(0xffffffffu, s0, 1); s0 += __shfl_xor_sync(0xffffffffu, s0, 2);
            q0 += __shfl_xor_sync(0xffffffffu, q0, 1); q0 += __shfl_xor_sync(0xffffffffu, q0, 2);
            s1 += __shfl_xor_sync(0xffffffffu, s1, 1); s1 += __shfl_xor_sync(0xffffffffu, s1, 2);
            q1 += __shfl_xor_sync(0xffffffffu, q1, 1); q1 += __shfl_xor_sync(0xffffffffu, q1, 2);
            if (tq == 0) {
                const int rl = wm * 64 + mf * 16 + g;
                redS[rl][wn] = s0; redQ[rl][wn] = q0;
                redS[rl + 8][wn] = s1; redQ[rl + 8][wn] = q1;
            }
        }
        __syncthreads();
#pragma unroll
        for (int mf = 0; mf < 4; mf++) {
            const int rl = wm * 64 + mf * 16 + g;
            const int m0 = row0 + rl, m1 = m0 + 8;
            float sum0 = redS[rl][0] + redS[rl][1] + redS[rl][2] + redS[rl][3];
            float sq0  = redQ[rl][0] + redQ[rl][1] + redQ[rl][2] + redQ[rl][3];
            float sum1 = redS[rl+8][0] + redS[rl+8][1] + redS[rl+8][2] + redS[rl+8][3];
            float sq1  = redQ[rl+8][0] + redQ[rl+8][1] + redQ[rl+8][2] + redQ[rl+8][3];
            float mean0 = sum0 * (1.f/128.f);
            float mean1 = sum1 * (1.f/128.f);
            float rstd0 = rsqrtf(sq0 * (1.f/128.f) - mean0*mean0 + 1e-5f);
            float rstd1 = rsqrtf(sq1 * (1.f/128.f) - mean1*mean1 + 1e-5f);
#pragma unroll
            for (int nf = 0; nf < 4; nf++) {
                const int c = wn * 32 + nf * 8 + tq * 2;
                float y0 = (acc[mf][nf][0] - mean0) * rstd0 * lng_s[c]   + lnb_s[c];
                float y1 = (acc[mf][nf][1] - mean0) * rstd0 * lng_s[c+1] + lnb_s[c+1];
                float y2 = (acc[mf][nf][2] - mean1) * rstd1 * lng_s[c]   + lnb_s[c];
                float y3 = (acc[mf][nf][3] - mean1) * rstd1 * lng_s[c+1] + lnb_s[c+1];
                *reinterpret_cast<float2*>(outF + (size_t)m0 * 128 + c) = make_float2(y0, y1);
                *reinterpret_cast<float2*>(outF + (size_t)m1 * 128 + c) = make_float2(y2, y3);
                *reinterpret_cast<uint32_t*>(outB + (size_t)m0 * 128 + c) = packbf2(y0, y1);
                *reinterpret_cast<uint32_t*>(outB + (size_t)m1 * 128 + c) = packbf2(y2, y3);
            }
        }
    } else {
#pragma unroll
        for (int mf = 0; mf < 4; mf++) {
            const int m0 = row0 + wm * 64 + mf * 16 + g;
            const int m1 = m0 + 8;
#pragma unroll
            for (int nf = 0; nf < 4; nf++) {
                const int c = wn * 32 + nf * 8 + tq * 2;
                float v0 = acc[mf][nf][0] + bias_s[c];
                float v1 = acc[mf][nf][1] + bias_s[c + 1];
                float v2 = acc[mf][nf][2] + bias_s[c];
                float v3 = acc[mf][nf][3] + bias_s[c + 1];
                if (EPI == 0) {
                    __nv_bfloat16* dst = (blockIdx.x == 0) ? qo : ((blockIdx.x == 1) ? ko : vo);
                    if (blockIdx.x == 0) { v0 *= QSCALE; v1 *= QSCALE; v2 *= QSCALE; v3 *= QSCALE; }
                    const int hh = c >> 5, dd = c & 31;
                    int b0i = m0 >> 11, s0i = m0 & 2047;
                    int b1i = m1 >> 11, s1i = m1 & 2047;
                    *reinterpret_cast<uint32_t*>(dst + ((size_t)(b0i * H_ + hh) * S_ + s0i) * DH_ + dd) = packbf2(v0, v1);
                    *reinterpret_cast<uint32_t*>(dst + ((size_t)(b1i * H_ + hh) * S_ + s1i) * DH_ + dd) = packbf2(v2, v3);
                } else {
                    *reinterpret_cast<uint32_t*>(outB + (size_t)m0 * Nstride + n0 + c) =
                        packbf2(fmaxf(v0, 0.f), fmaxf(v1, 0.f));
                    *reinterpret_cast<uint32_t*>(outB + (size_t)m1 * Nstride + n0 + c) =
                        packbf2(fmaxf(v2, 0.f), fmaxf(v3, 0.f));
                }
            }
        }
    }
}

// ======================= pipelined MMA flash attention (3-stage, Q-smem reused as stage 2) =======================
// CTA: (bh, 128 queries). 8 warps x 16 queries; 64-key tiles; Q pre-scaled -> ex2.
// Q region (10240 B) is read once into fragments at it==0, then recycled as
// pipeline stage 2 (K@0, V@5120). smem total 30720; 5 CTAs/SM target.
#define AT_SMEM 30720
#define NKV (S_ >> 6)
__global__ __launch_bounds__(256, 5)
void attn_kernel(const __nv_bfloat16* __restrict__ q, const __nv_bfloat16* __restrict__ k,
                 const __nv_bfloat16* __restrict__ v, __nv_bfloat16* __restrict__ out)
{
    extern __shared__ char smx[];
    const uint32_t sbase = cvta_s(smx);
    const uint32_t sQ = sbase;

    const int t    = threadIdx.x;
    const int wid  = t >> 5;
    const int lane = t & 31;
    const int g    = lane >> 2;
    const int tq   = lane & 3;
    const int bh   = blockIdx.y, b = bh >> 2, h = bh & 3;
    const int q0   = blockIdx.x * 128;

    // stage bases: stage 0/1 dedicated; stage 2 overlays the Q region
    const uint32_t kBase[3] = { sbase + 10240, sbase + 20480, sbase };
    const uint32_t vBase[3] = { sbase + 15360, sbase + 25600, sbase + 5120 };

    auto load_kv = [&](int tile, int stg) {
        const int j0 = tile << 6;
        int r = t >> 2, qq = t & 3;
        cp16(kBase[stg] + r * (TST*2) + qq * 16, &k[((size_t)bh * S_ + j0 + r) * DH_ + qq * 8]);
        cp16(vBase[stg] + r * (TST*2) + qq * 16, &v[((size_t)bh * S_ + j0 + r) * DH_ + qq * 8]);
    };

    // prologue: group0 = Q + KV0, group1 = KV1
#pragma unroll
    for (int i = 0; i < 2; i++) {
        int id = t + (i << 8);
        int r = id >> 2, qq = id & 3;
        cp16(sQ + r * (TST*2) + qq * 16, &q[((size_t)bh * S_ + q0 + r) * DH_ + qq * 8]);
    }
    load_kv(0, 0);
    CP_COMMIT();
    load_kv(1, 1);
    CP_COMMIT();

    float o[4][4];
    float lg = 0.f, lg8 = 0.f;
#pragma unroll
    for (int nf = 0; nf < 4; nf++)
#pragma unroll
        for (int e = 0; e < 4; e++) o[nf][e] = 0.f;

    uint32_t af2[2][4];

    const int aRow = wid * 16 + (lane & 15);
    const int aColX = (lane >> 4) * 8;
    const int bRow = (lane & 7) + ((lane >> 4) << 3);
    const int bColX = ((lane >> 3) & 1) * 8;
    const int vRow = (lane & 7) + (((lane >> 3) & 1) << 3);
    const int vColX = (lane >> 4) * 8;

    for (int it = 0; it < NKV; it++) {
        const int stg = it % 3;
        if (it < NKV - 1) CP_WAIT(1); else CP_WAIT(0);
        __syncthreads();

        if (it == 0) {
            // read Q into fragments BEFORE stage-2 prefetch overwrites the region
#pragma unroll
            for (int ks = 0; ks < 2; ks++)
                ldm_x4(af2[ks], sQ + (aRow * TST + ks * 16 + aColX) * 2);
            __syncthreads();   // all warps done reading Q
        }
        if (it + 2 < NKV) { load_kv(it + 2, (it + 2) % 3); CP_COMMIT(); }

        // scores = Q @ K^T
        float sc[8][4];
#pragma unroll
        for (int nf = 0; nf < 8; nf++)
#pragma unroll
            for (int e = 0; e < 4; e++) sc[nf][e] = 0.f;
#pragma unroll
        for (int ks = 0; ks < 2; ks++) {
            const int kk = ks << 4;
#pragma unroll
            for (int pp = 0; pp < 4; pp++) {
                uint32_t r4[4];
                ldm_x4(r4, kBase[stg] + ((pp * 16 + bRow) * TST + kk + bColX) * 2);
                uint32_t b0[2] = { r4[0], r4[1] }, b1[2] = { r4[2], r4[3] };
                mma16816(sc[pp*2],   af2[ks], b0);
                mma16816(sc[pp*2+1], af2[ks], b1);
            }
        }

        // p = ex2(s) (Q pre-scaled); accumulate l; pack PV A-fragments
        uint32_t pb[8][2];
#pragma unroll
        for (int nf = 0; nf < 8; nf++) {
            float p0 = ex2f(sc[nf][0]);
            float p1 = ex2f(sc[nf][1]);
            float p2 = ex2f(sc[nf][2]);
            float p3 = ex2f(sc[nf][3]);
            lg  += p0 + p1;
            lg8 += p2 + p3;
            pb[nf][0] = packbf2(p0, p1);
            pb[nf][1] = packbf2(p2, p3);
        }

        // O += P @ V
#pragma unroll
        for (int kf = 0; kf < 4; kf++) {
            uint32_t a4[4] = { pb[2*kf][0], pb[2*kf][1], pb[2*kf+1][0], pb[2*kf+1][1] };
#pragma unroll
            for (int pp = 0; pp < 2; pp++) {
                uint32_t r4[4];
                ldm_x4t(r4, vBase[stg] + ((kf * 16 + vRow) * TST + pp * 16 + vColX) * 2);
                uint32_t b0[2] = { r4[0], r4[1] }, b1[2] = { r4[2], r4[3] };
                mma16816(o[pp*2],   a4, b0);
                mma16816(o[pp*2+1], a4, b1);
            }
        }
    }

    lg  += __shfl_xor_sync(0xffffffffu, lg, 1);
    lg  += __shfl_xor_sync(0xffffffffu, lg, 2);
    lg8 += __shfl_xor_sync(0xffffffffu, lg8, 1);
    lg8 += __shfl_xor_sync(0xffffffffu, lg8, 2);
    const float inv0 = 1.f / lg;
    const float inv1 = 1.f / lg8;

    const int r0 = q0 + wid * 16 + g;
    const int r1 = r0 + 8;
#pragma unroll
    for (int nf = 0; nf < 4; nf++) {
        const int dd = nf * 8 + tq * 2;
        *reinterpret_cast<uint32_t*>(out + ((size_t)(b * S_ + r0)) * D_ + h * DH_ + dd) =
            packbf2(o[nf][0] * inv0, o[nf][1] * inv0);
        *reinterpret_cast<uint32_t*>(out + ((size_t)(b * S_ + r1)) * D_ + h * DH_ + dd) =
            packbf2(o[nf][2] * inv1, o[nf][3] * inv1);
    }
}

// ======================= Head: FC -> softmax -> rebalance =======================
__global__ __launch_bounds__(512)
void head_kernel(const float* __restrict__ hbuf, const float* __restrict__ fcw,
                 const float* __restrict__ fcb, float* __restrict__ out)
{
    __shared__ float logits[B_][OUT_];
    const int t = threadIdx.x;
    if (t < B_ * OUT_) {
        int b = t / OUT_;
        int o = t % OUT_;
        const float* hr = hbuf + ((size_t)(b * S_ + (S_ - 1))) * D_;
        float acc = fcb[o];
        for (int d = 0; d < D_; d++) acc += hr[d] * fcw[o * D_ + d];
        logits[b][o] = acc;
    }
    __syncthreads();
    if (t < B_) {
        const float UB = 0.3f, LB = 0.0f;
        float wv[OUT_], old[OUT_], wc[OUT_], res[OUT_];
        float mx = -1e30f;
        for (int o = 0; o < OUT_; o++) mx = fmaxf(mx, logits[t][o]);
        float sum = 0.f;
        for (int o = 0; o < OUT_; o++) { wv[o] = expf(logits[t][o] - mx); sum += wv[o]; }
        float inv = 1.f / sum;
        for (int o = 0; o < OUT_; o++) wv[o] *= inv;
        bool done = false;
        for (int o = 0; o < OUT_; o++) {
            old[o] = wv[o];
            wc[o]  = fminf(fmaxf(wv[o], LB), UB);
            res[o] = wv[o];
        }
        for (int it = 0; it < 16; it++) {
            float leftover = 0.f;
            for (int o = 0; o < OUT_; o++) leftover += old[o] - wc[o];
            float denom = 0.f;
            float noms[OUT_];
            for (int o = 0; o < OUT_; o++) {
                noms[o] = (wc[o] != UB) ? wc[o] : 0.f;
                denom += noms[o];
            }
            if (denom == 0.f) denom = 1.f;
            float cand[OUT_];
            bool any = false;
            for (int o = 0; o < OUT_; o++) {
                cand[o] = wc[o] + leftover * noms[o] / denom;
                if (cand[o] > UB) any = true;
            }
            if (!done)
                for (int o = 0; o < OUT_; o++) res[o] = cand[o];
            done = done || !any;
            if (!done) {
                for (int o = 0; o < OUT_; o++) {
                    old[o] = cand[o];
                    wc[o]  = fminf(fmaxf(cand[o], LB), UB);
                }
            }
        }
        for (int o = 0; o < OUT_; o++) out[t * OUT_ + o] = res[o];
    }
}

// ======================= launch =======================
extern "C" void kernel_launch(void* const* d_in, const int* in_sizes, int n_in,
                              void* d_out, int out_size)
{
    const float* x   = (const float*)d_in[0];
    const float* ipw = (const float*)d_in[1];
    const float* ipb = (const float*)d_in[2];
    const float* ow  = (const float*)d_in[3];
    const float* ob  = (const float*)d_in[4];
    const float* l1g = (const float*)d_in[5];
    const float* l1b = (const float*)d_in[6];
    const float* f1w = (const float*)d_in[7];
    const float* f1b = (const float*)d_in[8];
    const float* f2w = (const float*)d_in[9];
    const float* f2b = (const float*)d_in[10];
    const float* l2g = (const float*)d_in[11];
    const float* l2b = (const float*)d_in[12];
    const float* fcw = (const float*)d_in[13];
    const float* fcb = (const float*)d_in[14];

    __nv_bfloat16 *qb, *kb, *vb, *attnb, *hb, *ffb, *wip, *wout, *wf1, *wf2;
    float *h;
    cudaGetSymbolAddress((void**)&qb,    g_qb);
    cudaGetSymbolAddress((void**)&kb,    g_kb);
    cudaGetSymbolAddress((void**)&vb,    g_vb);
    cudaGetSymbolAddress((void**)&attnb, g_attnb);
    cudaGetSymbolAddress((void**)&hb,    g_hb);
    cudaGetSymbolAddress((void**)&h,     g_h);
    cudaGetSymbolAddress((void**)&ffb,   g_ffb);
    cudaGetSymbolAddress((void**)&wip,   g_wip);
    cudaGetSymbolAddress((void**)&wout,  g_wout);
    cudaGetSymbolAddress((void**)&wf1,   g_wf1);
    cudaGetSymbolAddress((void**)&wf2,   g_wf2);

    cudaFuncSetAttribute(mm_kernel<0>, cudaFuncAttributeMaxDynamicSharedMemorySize, MM_SMEM);
    cudaFuncSetAttribute(mm_kernel<1>, cudaFuncAttributeMaxDynamicSharedMemorySize, MM_SMEM);
    cudaFuncSetAttribute(mm_kernel<2>, cudaFuncAttributeMaxDynamicSharedMemorySize, MM_SMEM);
    cudaFuncSetAttribute(attn_kernel,  cudaFuncAttributeMaxDynamicSharedMemorySize, AT_SMEM);

    cvt_kernel<<<(L_*3*D_*D_)/1024, 256>>>(ipw, wip, L_*3*D_*D_);   // launch 0
    cvt_kernel<<<(M_*D_)/1024,      256>>>(x,   hb,  M_*D_);        // launch 1

    for (int l = 0; l < L_; l++) {
        const float* hinF = (l == 0) ? x : h;

        // QKV projection -> q/k/v bf16 [b,h,s,32] (q pre-scaled)
        mm_kernel<0><<<dim3(3, M_/128), 256, MM_SMEM>>>(
            hb, wip + (size_t)l*3*D_*D_, ipb + (size_t)l*3*D_,
            nullptr, nullptr, nullptr, nullptr, nullptr, qb, kb, vb, 3*D_, D_);

        // flash attention
        attn_kernel<<<dim3(S_/128, B_*H_), 256, AT_SMEM>>>(qb, kb, vb, attnb);

        if (l == 0) cvt_kernel<<<(L_*D_*D_)/1024, 256>>>(ow, wout, L_*D_*D_);

        // out projection + residual + LN1 -> h, hb
        mm_kernel<2><<<dim3(1, M_/128), 256, MM_SMEM>>>(
            attnb, wout + (size_t)l*D_*D_, ob + (size_t)l*D_,
            hinF, l1g + (size_t)l*D_, l1b + (size_t)l*D_,
            h, hb, nullptr, nullptr, nullptr, D_, D_);

        if (l == 0) cvt_kernel<<<(L_*FF_*D_)/1024, 256>>>(f1w, wf1, L_*FF_*D_);

        // FF1 + relu -> ffb (bf16)
        mm_kernel<1><<<dim3(FF_/128, M_/128), 256, MM_SMEM>>>(
            hb, wf1 + (size_t)l*FF_*D_, f1b + (size_t)l*FF_,
            nullptr, nullptr, nullptr, nullptr, ffb, nullptr, nullptr, nullptr, FF_, D_);

        if (l == 0) cvt_kernel<<<(L_*D_*FF_)/1024, 256>>>(f2w, wf2, L_*D_*FF_);

        // FF2 + residual(h) + LN2 -> h, hb
        mm_kernel<2><<<dim3(1, M_/128), 256, MM_SMEM>>>(
            ffb, wf2 + (size_t)l*D_*FF_, f2b + (size_t)l*D_,
            h, l2g + (size_t)l*D_, l2b + (size_t)l*D_,
            h, hb, nullptr, nullptr, nullptr, D_, FF_);
    }

    head_kernel<<<1, 512>>>(h, fcw, fcb, (float*)d_out);
}

// round 10
// speedup vs baseline: 1.0688x; 1.0494x over previous
#include <cuda_runtime.h>
#include <cuda_bf16.h>
#include <cuda_fp16.h>
#include <cstdint>
#include <math.h>

#define B_   16
#define S_   2048
#define D_   128
#define H_   4
#define DH_  32
#define FF_  512
#define L_   4
#define OUT_ 30
#define M_   (B_*S_)   // 32768

// log2(e) / sqrt(32): folded into Q so softmax is a bare ex2
#define QSCALE 0.25506626866f

// ======================= low-level helpers =======================
__device__ __forceinline__ void mma16816(float* d, const uint32_t* a, const uint32_t* b) {
    asm volatile("mma.sync.aligned.m16n8k16.row.col.f32.bf16.bf16.f32 "
        "{%0,%1,%2,%3}, {%4,%5,%6,%7}, {%8,%9}, {%0,%1,%2,%3};"
        : "+f"(d[0]), "+f"(d[1]), "+f"(d[2]), "+f"(d[3])
        : "r"(a[0]), "r"(a[1]), "r"(a[2]), "r"(a[3]), "r"(b[0]), "r"(b[1]));
}
// f16 variant (for P@V: P/V in f16, fp32 accum)
__device__ __forceinline__ void mma16816h(float* d, const uint32_t* a, const uint32_t* b) {
    asm volatile("mma.sync.aligned.m16n8k16.row.col.f32.f16.f16.f32 "
        "{%0,%1,%2,%3}, {%4,%5,%6,%7}, {%8,%9}, {%0,%1,%2,%3};"
        : "+f"(d[0]), "+f"(d[1]), "+f"(d[2]), "+f"(d[3])
        : "r"(a[0]), "r"(a[1]), "r"(a[2]), "r"(a[3]), "r"(b[0]), "r"(b[1]));
}
__device__ __forceinline__ uint32_t packbf2(float x, float y) {
    __nv_bfloat162 p = __floats2bfloat162_rn(x, y);
    return *(uint32_t*)&p;
}
__device__ __forceinline__ uint32_t packhf2(float x, float y) {
    __half2 p = __floats2half2_rn(x, y);
    return *(uint32_t*)&p;
}
// pack two f32 into f16x2 (lo = first arg)
__device__ __forceinline__ uint32_t cvt2h(float lo, float hi) {
    uint32_t d; asm("cvt.rn.f16x2.f32 %0, %1, %2;" : "=r"(d) : "f"(hi), "f"(lo)); return d;
}
// 2^x on both f16 halves
__device__ __forceinline__ uint32_t ex2h2(uint32_t x) {
    uint32_t d; asm("ex2.approx.f16x2 %0, %1;" : "=r"(d) : "r"(x)); return d;
}
__device__ __forceinline__ uint32_t cvta_s(const void* p) {
    return (uint32_t)__cvta_generic_to_shared(p);
}
__device__ __forceinline__ void cp16(uint32_t dst, const void* src) {
    asm volatile("cp.async.cg.shared.global [%0], [%1], 16;" :: "r"(dst), "l"(src));
}
#define CP_COMMIT() asm volatile("cp.async.commit_group;" ::: "memory")
#define CP_WAIT(n)  asm volatile("cp.async.wait_group %0;" :: "n"(n) : "memory")
__device__ __forceinline__ void ldm_x4(uint32_t* r, uint32_t a) {
    asm volatile("ldmatrix.sync.aligned.m8n8.x4.shared.b16 {%0,%1,%2,%3}, [%4];"
        : "=r"(r[0]), "=r"(r[1]), "=r"(r[2]), "=r"(r[3]) : "r"(a));
}
__device__ __forceinline__ void ldm_x4t(uint32_t* r, uint32_t a) {
    asm volatile("ldmatrix.sync.aligned.m8n8.x4.trans.shared.b16 {%0,%1,%2,%3}, [%4];"
        : "=r"(r[0]), "=r"(r[1]), "=r"(r[2]), "=r"(r[3]) : "r"(a));
}

#define TST  40    // smem row stride (elements) for 32-wide tiles

// ======================= scratch (device globals) =======================
__device__ __nv_bfloat16 g_qb[B_*H_*S_*DH_];
__device__ __nv_bfloat16 g_kb[B_*H_*S_*DH_];
__device__ __nv_bfloat16 g_vb[B_*H_*S_*DH_];   // holds f16 bits (P@V runs in f16)
__device__ __nv_bfloat16 g_attnb[M_*D_];
__device__ __nv_bfloat16 g_hb[M_*D_];
__device__ float         g_h[M_*D_];
__device__ __nv_bfloat16 g_ffb[(size_t)M_*FF_];
__device__ __nv_bfloat16 g_wip[L_*3*D_*D_];
__device__ __nv_bfloat16 g_wout[L_*D_*D_];
__device__ __nv_bfloat16 g_wf1[L_*FF_*D_];
__device__ __nv_bfloat16 g_wf2[L_*D_*FF_];

// ======================= fp32 -> bf16 conversion =======================
__global__ __launch_bounds__(256) void cvt_kernel(const float* __restrict__ s,
                                                  __nv_bfloat16* __restrict__ d, int n) {
    int i = (blockIdx.x * 256 + threadIdx.x) * 4;
    if (i < n) {
        float4 v = *reinterpret_cast<const float4*>(s + i);
        *reinterpret_cast<uint2*>(d + i) = make_uint2(packbf2(v.x, v.y), packbf2(v.z, v.w));
    }
}

// ======================= pipelined bf16 MMA GEMM (3-stage) =======================
// (unchanged from R7 — protected; only the v-scatter packs f16 now)
#define MM_SMEM 67072
template<int EPI>
__global__ __launch_bounds__(256)
void mm_kernel(const __nv_bfloat16* __restrict__ A, const __nv_bfloat16* __restrict__ W,
               const float* __restrict__ bias, const float* __restrict__ R,
               const float* __restrict__ lng, const float* __restrict__ lnb,
               float* __restrict__ outF, __nv_bfloat16* __restrict__ outB,
               __nv_bfloat16* __restrict__ qo, __nv_bfloat16* __restrict__ ko,
               __nv_bfloat16* __restrict__ vo, int Nstride, int K)
{
    extern __shared__ char smx[];
    const uint32_t sbase = cvta_s(smx);
    float* bias_s = (float*)(smx + 61440);
    float* lng_s  = (float*)(smx + 61952);
    float* lnb_s  = (float*)(smx + 62464);
    float (*redS)[4] = (float(*)[4])(smx + 62976);
    float (*redQ)[4] = (float(*)[4])(smx + 65024);

    const int t    = threadIdx.x;
    const int wid  = t >> 5;
    const int lane = t & 31;
    const int g    = lane >> 2;
    const int tq   = lane & 3;
    const int wm   = wid >> 2;
    const int wn   = wid & 3;
    const int row0 = blockIdx.y * 128;
    const int n0   = blockIdx.x * 128;

    if (t < 128) {
        bias_s[t] = bias[n0 + t];
        if (EPI == 2) { lng_s[t] = lng[t]; lnb_s[t] = lnb[t]; }
    }

    auto sA = [&](int s) -> uint32_t { return sbase + s * 10240; };
    auto sB = [&](int s) -> uint32_t { return sbase + 30720 + s * 10240; };

    auto load_tile = [&](int kt, int stg) {
        const int k0 = kt << 5;
#pragma unroll
        for (int i = 0; i < 2; i++) {
            int id = t + (i << 8);
            int r = id >> 2, qq = id & 3;
            cp16(sA(stg) + r * (TST*2) + qq * 16, &A[(size_t)(row0 + r) * K + k0 + qq * 8]);
            cp16(sB(stg) + r * (TST*2) + qq * 16, &W[(size_t)(n0   + r) * K + k0 + qq * 8]);
        }
    };

    float acc[4][4][4];
#pragma unroll
    for (int mf = 0; mf < 4; mf++)
#pragma unroll
        for (int nf = 0; nf < 4; nf++)
#pragma unroll
            for (int e = 0; e < 4; e++) acc[mf][nf][e] = 0.f;

    const int nkt = K >> 5;
    load_tile(0, 0); CP_COMMIT();
    if (nkt > 1) { load_tile(1, 1); CP_COMMIT(); }

    const int aRow = wm * 64 + (lane & 15);
    const int aColX = (lane >> 4) * 8;
    const int bRow = wn * 32 + (lane & 7) + ((lane >> 4) << 3);
    const int bColX = ((lane >> 3) & 1) * 8;

    for (int kt = 0; kt < nkt; kt++) {
        const int stg = kt % 3;
        if (kt < nkt - 1) CP_WAIT(1); else CP_WAIT(0);
        __syncthreads();
        if (kt + 2 < nkt) { load_tile(kt + 2, (kt + 2) % 3); CP_COMMIT(); }

#pragma unroll
        for (int ks = 0; ks < 2; ks++) {
            const int kk = ks << 4;
            uint32_t af[4][4];
#pragma unroll
            for (int mf = 0; mf < 4; mf++)
                ldm_x4(af[mf], sA(stg) + ((aRow + mf * 16) * TST + kk + aColX) * 2);
            uint32_t bf[4][2];
#pragma unroll
            for (int pp = 0; pp < 2; pp++) {
                uint32_t r4[4];
                ldm_x4(r4, sB(stg) + ((bRow + pp * 16) * TST + kk + bColX) * 2);
                bf[pp*2][0] = r4[0]; bf[pp*2][1] = r4[1];
                bf[pp*2+1][0] = r4[2]; bf[pp*2+1][1] = r4[3];
            }
#pragma unroll
            for (int mf = 0; mf < 4; mf++)
#pragma unroll
                for (int nf = 0; nf < 4; nf++)
                    mma16816(acc[mf][nf], af[mf], bf[nf]);
        }
    }

    // ---- epilogue ----
    if (EPI == 2) {
#pragma unroll
        for (int mf = 0; mf < 4; mf++) {
            const int m0 = row0 + wm * 64 + mf * 16 + g;
            const int m1 = m0 + 8;
            float s0 = 0.f, q0 = 0.f, s1 = 0.f, q1 = 0.f;
#pragma unroll
            for (int nf = 0; nf < 4; nf++) {
                const int c = wn * 32 + nf * 8 + tq * 2;
                float2 r0 = *reinterpret_cast<const float2*>(R + (size_t)m0 * 128 + c);
                float2 r1 = *reinterpret_cast<const float2*>(R + (size_t)m1 * 128 + c);
                float v0 = acc[mf][nf][0] + bias_s[c]     + r0.x;
                float v1 = acc[mf][nf][1] + bias_s[c + 1] + r0.y;
                float v2 = acc[mf][nf][2] + bias_s[c]     + r1.x;
                float v3 = acc[mf][nf][3] + bias_s[c + 1] + r1.y;
                acc[mf][nf][0] = v0; acc[mf][nf][1] = v1;
                acc[mf][nf][2] = v2; acc[mf][nf][3] = v3;
                s0 += v0 + v1; q0 += v0*v0 + v1*v1;
                s1 += v2 + v3; q1 += v2*v2 + v3*v3;
            }
            s0 += __shfl_xor_sync(0xffffffffu, s0, 1); s0 += __shfl_xor_sync(0xffffffffu, s0, 2);
            q0 += __shfl_xor_sync(0xffffffffu, q0, 1); q0 += __shfl_xor_sync(0xffffffffu, q0, 2);
            s1 += __shfl_xor_sync(0xffffffffu, s1, 1); s1 += __shfl_xor_sync(0xffffffffu, s1, 2);
            q1 += __shfl_xor_sync(0xffffffffu, q1, 1); q1 += __shfl_xor_sync(0xffffffffu, q1, 2);
            if (tq == 0) {
                const int rl = wm * 64 + mf * 16 + g;
                redS[rl][wn] = s0; redQ[rl][wn] = q0;
                redS[rl + 8][wn] = s1; redQ[rl + 8][wn] = q1;
            }
        }
        __syncthreads();
#pragma unroll
        for (int mf = 0; mf < 4; mf++) {
            const int rl = wm * 64 + mf * 16 + g;
            const int m0 = row0 + rl, m1 = m0 + 8;
            float sum0 = redS[rl][0] + redS[rl][1] + redS[rl][2] + redS[rl][3];
            float sq0  = redQ[rl][0] + redQ[rl][1] + redQ[rl][2] + redQ[rl][3];
            float sum1 = redS[rl+8][0] + redS[rl+8][1] + redS[rl+8][2] + redS[rl+8][3];
            float sq1  = redQ[rl+8][0] + redQ[rl+8][1] + redQ[rl+8][2] + redQ[rl+8][3];
            float mean0 = sum0 * (1.f/128.f);
            float mean1 = sum1 * (1.f/128.f);
            float rstd0 = rsqrtf(sq0 * (1.f/128.f) - mean0*mean0 + 1e-5f);
            float rstd1 = rsqrtf(sq1 * (1.f/128.f) - mean1*mean1 + 1e-5f);
#pragma unroll
            for (int nf = 0; nf < 4; nf++) {
                const int c = wn * 32 + nf * 8 + tq * 2;
                float y0 = (acc[mf][nf][0] - mean0) * rstd0 * lng_s[c]   + lnb_s[c];
                float y1 = (acc[mf][nf][1] - mean0) * rstd0 * lng_s[c+1] + lnb_s[c+1];
                float y2 = (acc[mf][nf][2] - mean1) * rstd1 * lng_s[c]   + lnb_s[c];
                float y3 = (acc[mf][nf][3] - mean1) * rstd1 * lng_s[c+1] + lnb_s[c+1];
                *reinterpret_cast<float2*>(outF + (size_t)m0 * 128 + c) = make_float2(y0, y1);
                *reinterpret_cast<float2*>(outF + (size_t)m1 * 128 + c) = make_float2(y2, y3);
                *reinterpret_cast<uint32_t*>(outB + (size_t)m0 * 128 + c) = packbf2(y0, y1);
                *reinterpret_cast<uint32_t*>(outB + (size_t)m1 * 128 + c) = packbf2(y2, y3);
            }
        }
    } else {
#pragma unroll
        for (int mf = 0; mf < 4; mf++) {
            const int m0 = row0 + wm * 64 + mf * 16 + g;
            const int m1 = m0 + 8;
#pragma unroll
            for (int nf = 0; nf < 4; nf++) {
                const int c = wn * 32 + nf * 8 + tq * 2;
                float v0 = acc[mf][nf][0] + bias_s[c];
                float v1 = acc[mf][nf][1] + bias_s[c + 1];
                float v2 = acc[mf][nf][2] + bias_s[c];
                float v3 = acc[mf][nf][3] + bias_s[c + 1];
                if (EPI == 0) {
                    __nv_bfloat16* dst = (blockIdx.x == 0) ? qo : ((blockIdx.x == 1) ? ko : vo);
                    if (blockIdx.x == 0) { v0 *= QSCALE; v1 *= QSCALE; v2 *= QSCALE; v3 *= QSCALE; }
                    const int hh = c >> 5, dd = c & 31;
                    int b0i = m0 >> 11, s0i = m0 & 2047;
                    int b1i = m1 >> 11, s1i = m1 & 2047;
                    uint32_t p0, p1;
                    if (blockIdx.x == 2) { p0 = packhf2(v0, v1); p1 = packhf2(v2, v3); }  // V -> f16
                    else                 { p0 = packbf2(v0, v1); p1 = packbf2(v2, v3); }
                    *reinterpret_cast<uint32_t*>(dst + ((size_t)(b0i * H_ + hh) * S_ + s0i) * DH_ + dd) = p0;
                    *reinterpret_cast<uint32_t*>(dst + ((size_t)(b1i * H_ + hh) * S_ + s1i) * DH_ + dd) = p1;
                } else {
                    *reinterpret_cast<uint32_t*>(outB + (size_t)m0 * Nstride + n0 + c) =
                        packbf2(fmaxf(v0, 0.f), fmaxf(v1, 0.f));
                    *reinterpret_cast<uint32_t*>(outB + (size_t)m1 * Nstride + n0 + c) =
                        packbf2(fmaxf(v2, 0.f), fmaxf(v3, 0.f));
                }
            }
        }
    }
}

// ======================= pipelined MMA flash attention (R7 structure + f16 softmax/PV) =======================
// CTA: (bh, 128 queries). 8 warps x 16 queries; 64-key tiles; Q pre-scaled -> ex2.
// softmax: cvt f32x2->f16x2 + ex2.approx.f16x2 (half the MUFU ops); P,V in f16.
// l computed by an extra n=8 MMA against a register-built ones column (fp32 exact).
#define AT_SMEM 40960
#define NKV (S_ >> 6)
__global__ __launch_bounds__(256, 4)
void attn_kernel(const __nv_bfloat16* __restrict__ q, const __nv_bfloat16* __restrict__ k,
                 const __nv_bfloat16* __restrict__ v, __nv_bfloat16* __restrict__ out)
{
    extern __shared__ char smx[];
    const uint32_t sbase = cvta_s(smx);
    const uint32_t sQ = sbase;

    const int t    = threadIdx.x;
    const int wid  = t >> 5;
    const int lane = t & 31;
    const int g    = lane >> 2;
    const int tq   = lane & 3;
    const int bh   = blockIdx.y, b = bh >> 2, h = bh & 3;
    const int q0   = blockIdx.x * 128;

    auto sK = [&](int s) -> uint32_t { return sbase + 10240 + s * 10240; };
    auto sV = [&](int s) -> uint32_t { return sbase + 15360 + s * 10240; };

    auto load_kv = [&](int tile, int stg) {
        const int j0 = tile << 6;
        int r = t >> 2, qq = t & 3;
        cp16(sK(stg) + r * (TST*2) + qq * 16, &k[((size_t)bh * S_ + j0 + r) * DH_ + qq * 8]);
        cp16(sV(stg) + r * (TST*2) + qq * 16, &v[((size_t)bh * S_ + j0 + r) * DH_ + qq * 8]);
    };

    // prologue
#pragma unroll
    for (int i = 0; i < 2; i++) {
        int id = t + (i << 8);
        int r = id >> 2, qq = id & 3;
        cp16(sQ + r * (TST*2) + qq * 16, &q[((size_t)bh * S_ + q0 + r) * DH_ + qq * 8]);
    }
    load_kv(0, 0);
    CP_COMMIT();
    load_kv(1, 1);
    CP_COMMIT();

    float o[4][4];
    float ol[4];   // ones-column accumulator: ol[0]=l(row g), ol[2]=l(row g+8) in col-0 lanes
#pragma unroll
    for (int nf = 0; nf < 4; nf++)
#pragma unroll
        for (int e = 0; e < 4; e++) o[nf][e] = 0.f;
#pragma unroll
    for (int e = 0; e < 4; e++) ol[e] = 0.f;

    uint32_t af2[2][4];
    const uint32_t vone = (lane < 4) ? 0x3C003C00u : 0u;   // f16 {1,1} in B n-col 0

    const int aRow = wid * 16 + (lane & 15);
    const int aColX = (lane >> 4) * 8;
    const int bRow = (lane & 7) + ((lane >> 4) << 3);
    const int bColX = ((lane >> 3) & 1) * 8;
    const int vRow = (lane & 7) + (((lane >> 3) & 1) << 3);
    const int vColX = (lane >> 4) * 8;

    for (int it = 0; it < NKV; it++) {
        const int stg = it % 3;
        if (it < NKV - 1) CP_WAIT(1); else CP_WAIT(0);
        __syncthreads();
        if (it + 2 < NKV) { load_kv(it + 2, (it + 2) % 3); CP_COMMIT(); }

        if (it == 0) {
#pragma unroll
            for (int ks = 0; ks < 2; ks++)
                ldm_x4(af2[ks], sQ + (aRow * TST + ks * 16 + aColX) * 2);
        }

        // scores = Q @ K^T (bf16)
        float sc[8][4];
#pragma unroll
        for (int nf = 0; nf < 8; nf++)
#pragma unroll
            for (int e = 0; e < 4; e++) sc[nf][e] = 0.f;
#pragma unroll
        for (int ks = 0; ks < 2; ks++) {
            const int kk = ks << 4;
#pragma unroll
            for (int pp = 0; pp < 4; pp++) {
                uint32_t r4[4];
                ldm_x4(r4, sK(stg) + ((pp * 16 + bRow) * TST + kk + bColX) * 2);
                uint32_t b0[2] = { r4[0], r4[1] }, b1[2] = { r4[2], r4[3] };
                mma16816(sc[pp*2],   af2[ks], b0);
                mma16816(sc[pp*2+1], af2[ks], b1);
            }
        }

        // p = ex2(s) in f16x2 (Q pre-scaled by log2e/sqrt(dh)); P packed directly
        uint32_t pb[8][2];
#pragma unroll
        for (int nf = 0; nf < 8; nf++) {
            pb[nf][0] = ex2h2(cvt2h(sc[nf][0], sc[nf][1]));
            pb[nf][1] = ex2h2(cvt2h(sc[nf][2], sc[nf][3]));
        }

        // O += P @ V (f16); l += P @ ones (register B-frag, fp32 accum)
#pragma unroll
        for (int kf = 0; kf < 4; kf++) {
            uint32_t a4[4] = { pb[2*kf][0], pb[2*kf][1], pb[2*kf+1][0], pb[2*kf+1][1] };
            uint32_t bones[2] = { vone, vone };
            mma16816h(ol, a4, bones);
#pragma unroll
            for (int pp = 0; pp < 2; pp++) {
                uint32_t r4[4];
                ldm_x4t(r4, sV(stg) + ((kf * 16 + vRow) * TST + pp * 16 + vColX) * 2);
                uint32_t b0[2] = { r4[0], r4[1] }, b1[2] = { r4[2], r4[3] };
                mma16816h(o[pp*2],   a4, b0);
                mma16816h(o[pp*2+1], a4, b1);
            }
        }
    }

    // l lives in col-0 lanes (tq==0): broadcast across each quad
    const float lg  = __shfl_sync(0xffffffffu, ol[0], lane & ~3);
    const float lg8 = __shfl_sync(0xffffffffu, ol[2], lane & ~3);
    const float inv0 = 1.f / lg;
    const float inv1 = 1.f / lg8;

    const int r0 = q0 + wid * 16 + g;
    const int r1 = r0 + 8;
#pragma unroll
    for (int nf = 0; nf < 4; nf++) {
        const int dd = nf * 8 + tq * 2;
        *reinterpret_cast<uint32_t*>(out + ((size_t)(b * S_ + r0)) * D_ + h * DH_ + dd) =
            packbf2(o[nf][0] * inv0, o[nf][1] * inv0);
        *reinterpret_cast<uint32_t*>(out + ((size_t)(b * S_ + r1)) * D_ + h * DH_ + dd) =
            packbf2(o[nf][2] * inv1, o[nf][3] * inv1);
    }
}

// ======================= Head: FC -> softmax -> rebalance =======================
__global__ __launch_bounds__(512)
void head_kernel(const float* __restrict__ hbuf, const float* __restrict__ fcw,
                 const float* __restrict__ fcb, float* __restrict__ out)
{
    __shared__ float logits[B_][OUT_];
    const int t = threadIdx.x;
    if (t < B_ * OUT_) {
        int b = t / OUT_;
        int o = t % OUT_;
        const float* hr = hbuf + ((size_t)(b * S_ + (S_ - 1))) * D_;
        float acc = fcb[o];
        for (int d = 0; d < D_; d++) acc += hr[d] * fcw[o * D_ + d];
        logits[b][o] = acc;
    }
    __syncthreads();
    if (t < B_) {
        const float UB = 0.3f, LB = 0.0f;
        float wv[OUT_], old[OUT_], wc[OUT_], res[OUT_];
        float mx = -1e30f;
        for (int o = 0; o < OUT_; o++) mx = fmaxf(mx, logits[t][o]);
        float sum = 0.f;
        for (int o = 0; o < OUT_; o++) { wv[o] = expf(logits[t][o] - mx); sum += wv[o]; }
        float inv = 1.f / sum;
        for (int o = 0; o < OUT_; o++) wv[o] *= inv;
        bool done = false;
        for (int o = 0; o < OUT_; o++) {
            old[o] = wv[o];
            wc[o]  = fminf(fmaxf(wv[o], LB), UB);
            res[o] = wv[o];
        }
        for (int it = 0; it < 16; it++) {
            float leftover = 0.f;
            for (int o = 0; o < OUT_; o++) leftover += old[o] - wc[o];
            float denom = 0.f;
            float noms[OUT_];
            for (int o = 0; o < OUT_; o++) {
                noms[o] = (wc[o] != UB) ? wc[o] : 0.f;
                denom += noms[o];
            }
            if (denom == 0.f) denom = 1.f;
            float cand[OUT_];
            bool any = false;
            for (int o = 0; o < OUT_; o++) {
                cand[o] = wc[o] + leftover * noms[o] / denom;
                if (cand[o] > UB) any = true;
            }
            if (!done)
                for (int o = 0; o < OUT_; o++) res[o] = cand[o];
            done = done || !any;
            if (!done) {
                for (int o = 0; o < OUT_; o++) {
                    old[o] = cand[o];
                    wc[o]  = fminf(fmaxf(cand[o], LB), UB);
                }
            }
        }
        for (int o = 0; o < OUT_; o++) out[t * OUT_ + o] = res[o];
    }
}

// ======================= launch =======================
extern "C" void kernel_launch(void* const* d_in, const int* in_sizes, int n_in,
                              void* d_out, int out_size)
{
    const float* x   = (const float*)d_in[0];
    const float* ipw = (const float*)d_in[1];
    const float* ipb = (const float*)d_in[2];
    const float* ow  = (const float*)d_in[3];
    const float* ob  = (const float*)d_in[4];
    const float* l1g = (const float*)d_in[5];
    const float* l1b = (const float*)d_in[6];
    const float* f1w = (const float*)d_in[7];
    const float* f1b = (const float*)d_in[8];
    const float* f2w = (const float*)d_in[9];
    const float* f2b = (const float*)d_in[10];
    const float* l2g = (const float*)d_in[11];
    const float* l2b = (const float*)d_in[12];
    const float* fcw = (const float*)d_in[13];
    const float* fcb = (const float*)d_in[14];

    __nv_bfloat16 *qb, *kb, *vb, *attnb, *hb, *ffb, *wip, *wout, *wf1, *wf2;
    float *h;
    cudaGetSymbolAddress((void**)&qb,    g_qb);
    cudaGetSymbolAddress((void**)&kb,    g_kb);
    cudaGetSymbolAddress((void**)&vb,    g_vb);
    cudaGetSymbolAddress((void**)&attnb, g_attnb);
    cudaGetSymbolAddress((void**)&hb,    g_hb);
    cudaGetSymbolAddress((void**)&h,     g_h);
    cudaGetSymbolAddress((void**)&ffb,   g_ffb);
    cudaGetSymbolAddress((void**)&wip,   g_wip);
    cudaGetSymbolAddress((void**)&wout,  g_wout);
    cudaGetSymbolAddress((void**)&wf1,   g_wf1);
    cudaGetSymbolAddress((void**)&wf2,   g_wf2);

    cudaFuncSetAttribute(mm_kernel<0>, cudaFuncAttributeMaxDynamicSharedMemorySize, MM_SMEM);
    cudaFuncSetAttribute(mm_kernel<1>, cudaFuncAttributeMaxDynamicSharedMemorySize, MM_SMEM);
    cudaFuncSetAttribute(mm_kernel<2>, cudaFuncAttributeMaxDynamicSharedMemorySize, MM_SMEM);
    cudaFuncSetAttribute(attn_kernel,  cudaFuncAttributeMaxDynamicSharedMemorySize, AT_SMEM);

    cvt_kernel<<<(L_*3*D_*D_)/1024, 256>>>(ipw, wip, L_*3*D_*D_);   // launch 0
    cvt_kernel<<<(M_*D_)/1024,      256>>>(x,   hb,  M_*D_);        // launch 1

    for (int l = 0; l < L_; l++) {
        const float* hinF = (l == 0) ? x : h;

        // QKV projection -> q/k bf16, v f16 [b,h,s,32] (q pre-scaled)
        mm_kernel<0><<<dim3(3, M_/128), 256, MM_SMEM>>>(
            hb, wip + (size_t)l*3*D_*D_, ipb + (size_t)l*3*D_,
            nullptr, nullptr, nullptr, nullptr, nullptr, qb, kb, vb, 3*D_, D_);

        // flash attention
        attn_kernel<<<dim3(S_/128, B_*H_), 256, AT_SMEM>>>(qb, kb, vb, attnb);

        if (l == 0) cvt_kernel<<<(L_*D_*D_)/1024, 256>>>(ow, wout, L_*D_*D_);

        // out projection + residual + LN1 -> h, hb
        mm_kernel<2><<<dim3(1, M_/128), 256, MM_SMEM>>>(
            attnb, wout + (size_t)l*D_*D_, ob + (size_t)l*D_,
            hinF, l1g + (size_t)l*D_, l1b + (size_t)l*D_,
            h, hb, nullptr, nullptr, nullptr, D_, D_);

        if (l == 0) cvt_kernel<<<(L_*FF_*D_)/1024, 256>>>(f1w, wf1, L_*FF_*D_);

        // FF1 + relu -> ffb (bf16)
        mm_kernel<1><<<dim3(FF_/128, M_/128), 256, MM_SMEM>>>(
            hb, wf1 + (size_t)l*FF_*D_, f1b + (size_t)l*FF_,
            nullptr, nullptr, nullptr, nullptr, ffb, nullptr, nullptr, nullptr, FF_, D_);

        if (l == 0) cvt_kernel<<<(L_*D_*FF_)/1024, 256>>>(f2w, wf2, L_*D_*FF_);

        // FF2 + residual(h) + LN2 -> h, hb
        mm_kernel<2><<<dim3(1, M_/128), 256, MM_SMEM>>>(
            ffb, wf2 + (size_t)l*D_*FF_, f2b + (size_t)l*D_,
            h, l2g + (size_t)l*D_, l2b + (size_t)l*D_,
            h, hb, nullptr, nullptr, nullptr, D_, FF_);
    }

    head_kernel<<<1, 512>>>(h, fcw, fcb, (float*)d_out);
}